// round 1
// baseline (speedup 1.0000x reference)
#include <cuda_runtime.h>
#include <cstdint>

// ---------------------------------------------------------------------------
// GATNet: 2-layer multi-head graph attention, fp32 CUDA-core baseline.
//   B=16, N=1024, CIN=64, D=128, H=8, COUT=64
// Pipeline:
//   feat1:  H1[h][b*N+n][128] = flow_x[b*N+n][64] @ Wh[h]            (8 GEMMs)
//   attn1:  per (h,b): flash-attention with graph mask, epilogue adds bh[h],
//           leaky-relu, writes X2[b*N+n][h*128+j]  (the concat layout)
//   feat2:  H2[b*N+n][64] = X2 @ W_out
//   attn2:  per b: flash-attention, epilogue adds b_out, leaky-relu -> d_out
// ---------------------------------------------------------------------------

#define LOG2E 1.4426950408889634f

static const int NV   = 1024;   // nodes
static const int BV   = 16;     // batch
static const int DH   = 128;    // per-head hidden
static const int NHV  = 8;      // heads
static const int COUT = 64;

// scratch (no cudaMalloc allowed)
__device__ float g_H1[(size_t)NHV * BV * NV * DH];      // 67 MB
__device__ float g_X2[(size_t)BV * NV * (NHV * DH)];    // 64 MB
__device__ float g_H2[(size_t)BV * NV * COUT];          // 4 MB

// ---------------------------------------------------------------------------
// feat1: per-head feature GEMM. M=16384 rows, K=64, Ncols=128.
// Block: 256 threads, tile 128 rows x 128 cols, 8x8 microtile.
// ---------------------------------------------------------------------------
__global__ __launch_bounds__(256, 1)
void feat1_kernel(const float* __restrict__ x, const float* __restrict__ Wh,
                  float* __restrict__ H1)
{
    const int BMP = 132;
    extern __shared__ float sm[];
    float* Xs = sm;                // [64][132]  (k-major, transposed x tile)
    float* Ws = sm + 64 * BMP;     // [64][132]  (k-major, natural Wh layout)

    int tid = threadIdx.x, tx = tid & 15, ty = tid >> 4;
    int h = blockIdx.y;
    int rowbase = blockIdx.x * 128;
    const float* W = Wh + (size_t)h * 64 * 128;

    // load x tile transposed: Xs[k][row]
    for (int idx = tid; idx < 128 * 16; idx += 256) {
        int row = idx >> 4, c4 = idx & 15;
        float4 v = *(const float4*)(x + (size_t)(rowbase + row) * 64 + c4 * 4);
        Xs[(c4 * 4 + 0) * BMP + row] = v.x;
        Xs[(c4 * 4 + 1) * BMP + row] = v.y;
        Xs[(c4 * 4 + 2) * BMP + row] = v.z;
        Xs[(c4 * 4 + 3) * BMP + row] = v.w;
    }
    // load W straight: Ws[k][d]
    for (int idx = tid; idx < 64 * 32; idx += 256) {
        int k = idx >> 5, c4 = idx & 31;
        *(float4*)&Ws[k * BMP + c4 * 4] = *(const float4*)(W + k * 128 + c4 * 4);
    }
    __syncthreads();

    float acc[8][8];
#pragma unroll
    for (int r = 0; r < 8; r++)
#pragma unroll
        for (int u = 0; u < 8; u++) acc[r][u] = 0.0f;

#pragma unroll 4
    for (int k = 0; k < 64; k++) {
        float4 a0 = *(const float4*)&Xs[k * BMP + ty * 8];
        float4 a1 = *(const float4*)&Xs[k * BMP + ty * 8 + 4];
        float a[8] = {a0.x, a0.y, a0.z, a0.w, a1.x, a1.y, a1.z, a1.w};
        float b[8];
#pragma unroll
        for (int u = 0; u < 8; u++) b[u] = Ws[k * BMP + tx + 16 * u];
#pragma unroll
        for (int r = 0; r < 8; r++)
#pragma unroll
            for (int u = 0; u < 8; u++) acc[r][u] += a[r] * b[u];
    }

#pragma unroll
    for (int r = 0; r < 8; r++) {
        size_t ro = ((size_t)h * 16384 + rowbase + ty * 8 + r) * 128;
#pragma unroll
        for (int u = 0; u < 8; u++) H1[ro + tx + 16 * u] = acc[r][u];
    }
}

// ---------------------------------------------------------------------------
// feat2: H2 = X2 @ W_out. M=16384, K=1024, Ncols=64.
// Block: 256 threads, tile 128 rows x 64 cols, k-chunks of 64, 8x4 microtile.
// ---------------------------------------------------------------------------
__global__ __launch_bounds__(256, 1)
void feat2_kernel(const float* __restrict__ X2, const float* __restrict__ W,
                  float* __restrict__ H2)
{
    const int BMP = 132, BNP = 68;
    extern __shared__ float sm[];
    float* Xs = sm;               // [64][132]
    float* Ws = sm + 64 * BMP;    // [64][68]

    int tid = threadIdx.x, tx = tid & 15, ty = tid >> 4;
    int rowbase = blockIdx.x * 128;

    float acc[8][4];
#pragma unroll
    for (int r = 0; r < 8; r++)
#pragma unroll
        for (int u = 0; u < 4; u++) acc[r][u] = 0.0f;

    for (int kc = 0; kc < 16; kc++) {
        __syncthreads();
        for (int idx = tid; idx < 128 * 16; idx += 256) {
            int row = idx >> 4, c4 = idx & 15;
            float4 v = *(const float4*)(X2 + (size_t)(rowbase + row) * 1024 + kc * 64 + c4 * 4);
            Xs[(c4 * 4 + 0) * BMP + row] = v.x;
            Xs[(c4 * 4 + 1) * BMP + row] = v.y;
            Xs[(c4 * 4 + 2) * BMP + row] = v.z;
            Xs[(c4 * 4 + 3) * BMP + row] = v.w;
        }
        for (int idx = tid; idx < 64 * 16; idx += 256) {
            int k = idx >> 4, c4 = idx & 15;
            *(float4*)&Ws[k * BNP + c4 * 4] = *(const float4*)(W + (size_t)(kc * 64 + k) * 64 + c4 * 4);
        }
        __syncthreads();

#pragma unroll 4
        for (int k = 0; k < 64; k++) {
            float4 a0 = *(const float4*)&Xs[k * BMP + ty * 8];
            float4 a1 = *(const float4*)&Xs[k * BMP + ty * 8 + 4];
            float a[8] = {a0.x, a0.y, a0.z, a0.w, a1.x, a1.y, a1.z, a1.w};
            float b[4];
#pragma unroll
            for (int u = 0; u < 4; u++) b[u] = Ws[k * BNP + tx + 16 * u];
#pragma unroll
            for (int r = 0; r < 8; r++)
#pragma unroll
                for (int u = 0; u < 4; u++) acc[r][u] += a[r] * b[u];
        }
    }

#pragma unroll
    for (int r = 0; r < 8; r++) {
        size_t ro = (size_t)(rowbase + ty * 8 + r) * 64;
#pragma unroll
        for (int u = 0; u < 4; u++) H2[ro + tx + 16 * u] = acc[r][u];
    }
}

// ---------------------------------------------------------------------------
// Fused masked attention (flash-style, fp32):
//   out[i][:] = leaky_relu( softmax_m( mask(Q K^T) ) @ V + bias )
// Q = K = V = Hf slice [N][D]. Mask: s = dot * graph; s==0 -> -1e16.
// Grid: (N/128, B, Hheads). Block 256.  BM=128 query rows, BN=64 key chunk.
// smem: Qs[D][132] k-major, KsT[D][68] k-major, Vs[64][D+4] natural, Ps[64][132].
// All GEMM inner-loop smem loads are bank-conflict-free.
// ---------------------------------------------------------------------------
template <int D>
__global__ __launch_bounds__(256, 1)
void attn_kernel(const float* __restrict__ Hf, const float* __restrict__ graph,
                 const float* __restrict__ bias, float* __restrict__ out,
                 int out_stride)
{
    constexpr int BM = 128, BN = 64, BMP = 132, BNP = 68, DP = D + 4;
    constexpr int UO = D / 16;   // output cols per thread
    constexpr int NN = 1024;

    extern __shared__ float sm[];
    float* Qs  = sm;                       // D*BMP
    float* KsT = Qs + D * BMP;             // D*BNP
    float* Vs  = KsT + D * BNP;            // BN*DP
    float* Ps  = Vs + BN * DP;             // BN*BMP

    int tid = threadIdx.x, tx = tid & 15, ty = tid >> 4;
    int z = blockIdx.z, bb = blockIdx.y;
    int qbase = blockIdx.x * BM;

    const float* Hp = Hf + (size_t)(z * gridDim.y + bb) * NN * D;
    const float* bi = bias + (size_t)z * D;
    float* outp = out + (size_t)bb * NN * out_stride + (size_t)z * D;

    // Q tile transposed into smem: Qs[k][i]
    for (int idx = tid; idx < BM * (D / 4); idx += 256) {
        int row = idx / (D / 4), c4 = idx % (D / 4);
        float4 v = *(const float4*)(Hp + (size_t)(qbase + row) * D + c4 * 4);
        Qs[(c4 * 4 + 0) * BMP + row] = v.x;
        Qs[(c4 * 4 + 1) * BMP + row] = v.y;
        Qs[(c4 * 4 + 2) * BMP + row] = v.z;
        Qs[(c4 * 4 + 3) * BMP + row] = v.w;
    }

    float O[8][UO];
#pragma unroll
    for (int r = 0; r < 8; r++)
#pragma unroll
        for (int u = 0; u < UO; u++) O[r][u] = 0.0f;
    float mrow[8], lrow[8];
#pragma unroll
    for (int r = 0; r < 8; r++) { mrow[r] = -3.0e38f; lrow[r] = 0.0f; }

    for (int ch = 0; ch < NN / BN; ch++) {
        int kb = ch * BN;
        __syncthreads();   // prev GEMM2 done with KsT/Vs/Ps (also publishes Qs on ch==0)
        // load K/V chunk: both layouts
        for (int idx = tid; idx < BN * (D / 4); idx += 256) {
            int m = idx / (D / 4), c4 = idx % (D / 4);
            float4 v = *(const float4*)(Hp + (size_t)(kb + m) * D + c4 * 4);
            *(float4*)&Vs[m * DP + c4 * 4] = v;
            KsT[(c4 * 4 + 0) * BNP + m] = v.x;
            KsT[(c4 * 4 + 1) * BNP + m] = v.y;
            KsT[(c4 * 4 + 2) * BNP + m] = v.z;
            KsT[(c4 * 4 + 3) * BNP + m] = v.w;
        }
        __syncthreads();

        // GEMM1: S[i][m] = sum_k Q[i][k] K[m][k], rows i=ty*8+r, cols m=tx+16u
        float S[8][4];
#pragma unroll
        for (int r = 0; r < 8; r++)
#pragma unroll
            for (int u = 0; u < 4; u++) S[r][u] = 0.0f;
#pragma unroll 4
        for (int k = 0; k < D; k++) {
            float4 a0 = *(const float4*)&Qs[k * BMP + ty * 8];
            float4 a1 = *(const float4*)&Qs[k * BMP + ty * 8 + 4];
            float a[8] = {a0.x, a0.y, a0.z, a0.w, a1.x, a1.y, a1.z, a1.w};
            float bv[4];
#pragma unroll
            for (int u = 0; u < 4; u++) bv[u] = KsT[k * BNP + tx + 16 * u];
#pragma unroll
            for (int r = 0; r < 8; r++)
#pragma unroll
                for (int u = 0; u < 4; u++) S[r][u] += a[r] * bv[u];
        }

        // mask: s = dot * graph ; s==0 -> -1e16  (exactly like reference)
#pragma unroll
        for (int r = 0; r < 8; r++) {
            size_t grow = (size_t)(qbase + ty * 8 + r) * NN + kb;
#pragma unroll
            for (int u = 0; u < 4; u++) {
                float g = graph[grow + tx + 16 * u];
                float s = S[r][u] * g;
                S[r][u] = (s == 0.0f) ? -1e16f : s;
            }
        }

        // online softmax update (row state replicated across the 16 tx lanes)
#pragma unroll
        for (int r = 0; r < 8; r++) {
            float mx = S[r][0];
#pragma unroll
            for (int u = 1; u < 4; u++) mx = fmaxf(mx, S[r][u]);
            mx = fmaxf(mx, __shfl_xor_sync(0xffffffffu, mx, 1));
            mx = fmaxf(mx, __shfl_xor_sync(0xffffffffu, mx, 2));
            mx = fmaxf(mx, __shfl_xor_sync(0xffffffffu, mx, 4));
            mx = fmaxf(mx, __shfl_xor_sync(0xffffffffu, mx, 8));
            float mn = fmaxf(mrow[r], mx);
            float alpha = exp2f((mrow[r] - mn) * LOG2E);
            mrow[r] = mn;
            float rs = 0.0f;
#pragma unroll
            for (int u = 0; u < 4; u++) {
                float p = exp2f((S[r][u] - mn) * LOG2E);
                S[r][u] = p;
                rs += p;
            }
            rs += __shfl_xor_sync(0xffffffffu, rs, 1);
            rs += __shfl_xor_sync(0xffffffffu, rs, 2);
            rs += __shfl_xor_sync(0xffffffffu, rs, 4);
            rs += __shfl_xor_sync(0xffffffffu, rs, 8);
            lrow[r] = lrow[r] * alpha + rs;
#pragma unroll
            for (int u = 0; u < UO; u++) O[r][u] *= alpha;
        }

        // write P to smem: Ps[m][i]
#pragma unroll
        for (int u = 0; u < 4; u++) {
            int m = tx + 16 * u;
            float4 p0 = make_float4(S[0][u], S[1][u], S[2][u], S[3][u]);
            float4 p1 = make_float4(S[4][u], S[5][u], S[6][u], S[7][u]);
            *(float4*)&Ps[m * BMP + ty * 8]     = p0;
            *(float4*)&Ps[m * BMP + ty * 8 + 4] = p1;
        }
        __syncthreads();

        // GEMM2: O[i][j] += sum_m P[i][m] V[m][j]
#pragma unroll 2
        for (int m = 0; m < BN; m++) {
            float4 p0 = *(const float4*)&Ps[m * BMP + ty * 8];
            float4 p1 = *(const float4*)&Ps[m * BMP + ty * 8 + 4];
            float p[8] = {p0.x, p0.y, p0.z, p0.w, p1.x, p1.y, p1.z, p1.w};
            float vv[UO];
#pragma unroll
            for (int u = 0; u < UO; u++) vv[u] = Vs[m * DP + tx + 16 * u];
#pragma unroll
            for (int r = 0; r < 8; r++)
#pragma unroll
                for (int u = 0; u < UO; u++) O[r][u] += p[r] * vv[u];
        }
    }

    // epilogue: normalize, + bias, leaky relu, store
#pragma unroll
    for (int r = 0; r < 8; r++) {
        float inv = 1.0f / lrow[r];
        size_t ro = (size_t)(qbase + ty * 8 + r) * out_stride;
#pragma unroll
        for (int u = 0; u < UO; u++) {
            float v = O[r][u] * inv + bi[tx + 16 * u];
            v = (v > 0.0f) ? v : 0.01f * v;
            outp[ro + tx + 16 * u] = v;
        }
    }
}

// ---------------------------------------------------------------------------
// host launcher
// ---------------------------------------------------------------------------
extern "C" void kernel_launch(void* const* d_in, const int* in_sizes, int n_in,
                              void* d_out, int out_size)
{
    const float* x     = (const float*)d_in[0];   // [16,1024,64]
    const float* graph = (const float*)d_in[1];   // [1024,1024]
    const float* Wh    = (const float*)d_in[2];   // [8,64,128]
    const float* bh    = (const float*)d_in[3];   // [8,128]
    const float* W_out = (const float*)d_in[4];   // [1024,64]
    const float* b_out = (const float*)d_in[5];   // [64]
    float* out = (float*)d_out;                   // [16,1024,64]

    float *H1, *X2, *H2;
    cudaGetSymbolAddress((void**)&H1, g_H1);
    cudaGetSymbolAddress((void**)&X2, g_X2);
    cudaGetSymbolAddress((void**)&H2, g_H2);

    const int FEAT1_SMEM = (64 * 132) * 2 * 4;                                    // 67.6 KB
    const int FEAT2_SMEM = (64 * 132 + 64 * 68) * 4;                              // 51.2 KB
    const int ATTN1_SMEM = (128 * 132 + 128 * 68 + 64 * 132 + 64 * 132) * 4;      // 170 KB
    const int ATTN2_SMEM = (64 * 132 + 64 * 68 + 64 * 68 + 64 * 132) * 4;         // 102 KB

    cudaFuncSetAttribute(feat1_kernel, cudaFuncAttributeMaxDynamicSharedMemorySize, FEAT1_SMEM);
    cudaFuncSetAttribute(feat2_kernel, cudaFuncAttributeMaxDynamicSharedMemorySize, FEAT2_SMEM);
    cudaFuncSetAttribute(attn_kernel<128>, cudaFuncAttributeMaxDynamicSharedMemorySize, ATTN1_SMEM);
    cudaFuncSetAttribute(attn_kernel<64>, cudaFuncAttributeMaxDynamicSharedMemorySize, ATTN2_SMEM);

    // layer 1: features then fused masked attention (writes concat + leaky relu)
    feat1_kernel<<<dim3(128, 8), 256, FEAT1_SMEM>>>(x, Wh, H1);
    attn_kernel<128><<<dim3(8, 16, 8), 256, ATTN1_SMEM>>>(H1, graph, bh, X2, 1024);

    // layer 2
    feat2_kernel<<<dim3(128), 256, FEAT2_SMEM>>>(X2, W_out, H2);
    attn_kernel<64><<<dim3(8, 16, 1), 256, ATTN2_SMEM>>>(H2, graph, b_out, out, 64);
}